// round 2
// baseline (speedup 1.0000x reference)
#include <cuda_runtime.h>

// LSTM: B=128, T=2048, F=3, U=256. Persistent kernel, 128 CTAs = 16 batch-groups x 8 gate-column blocks.
// Each CTA: 8 batch rows x 32 units (128 permuted gate columns). Wh slice resident in SMEM.
// h exchanged through L2 (ping-pong __device__ buffers) with an 8-CTA per-group barrier each step.
// c stays in registers of its owning thread for all 2048 steps.

#define BB 128
#define TT 2048
#define FF 3
#define UU 256
#define G4 1024
#define NCTA 128
#define NTHR 256

__device__ float    g_h[2][BB * UU];     // ping-pong hidden state
__device__ unsigned g_bar[16 * 32];      // one counter per group, 128B apart

// SMEM layout (float offsets)
#define OFF_WH   0        // 256*128 = 32768  (permuted Wh slice: [k][unit_local*4+gate])
#define OFF_HS   32768    // 8*260   = 2080   (h tile, [b_local][k], row stride 260 (pad) )
#define OFF_BIAS 34848    // 128              (permuted bias slice)
#define OFF_WX   34976    // 3*128   = 384    (permuted Wx slice)
#define OFF_XS   35360    // 32               (x[t] tile: [b_local][f])
#define OFF_HN   35392    // 8*33    = 264    (h_new staging, padded)
#define OFF_CS   35656    // 8*33    = 264    (c staging for final write)
#define SMEM_FLOATS 35920
#define SMEM_BYTES (SMEM_FLOATS * 4)

__device__ __forceinline__ float sig_f(float x) {
    x = fminf(fmaxf(x, -30.f), 30.f);
    float e = __expf(-x);
    return __fdividef(1.f, 1.f + e);
}

__device__ __forceinline__ float tanh_f(float x) {
    float ax = fminf(fabsf(x), 15.f);
    float e = __expf(-2.f * ax);           // in (0,1]
    float r = __fdividef(1.f - e, 1.f + e);
    return copysignf(r, x);
}

__global__ void lstm_init_kernel() {
    int i = blockIdx.x * blockDim.x + threadIdx.x;
    if (i < 2 * BB * UU) ((float*)g_h)[i] = 0.f;
    if (i < 16 * 32) g_bar[i] = 0u;
}

__global__ void __launch_bounds__(NTHR, 1) lstm_persistent_kernel(
    const float* __restrict__ x,     // [B, T, F]
    const float* __restrict__ Wx,    // [F, 4U]
    const float* __restrict__ Wh,    // [U, 4U]
    const float* __restrict__ bias,  // [4U]
    float* __restrict__ out,         // ys [B,T,U] (+ h_T [B,U] + c_T [B,U] if write_hc)
    int write_hc)
{
    extern __shared__ float sm[];
    float* whs = sm + OFF_WH;
    float* hs  = sm + OFF_HS;
    float* bs  = sm + OFF_BIAS;
    float* wxs = sm + OFF_WX;
    float* xs  = sm + OFF_XS;
    float* hns = sm + OFF_HN;
    float* cs  = sm + OFF_CS;

    const int tid = threadIdx.x;
    const int RB  = blockIdx.x >> 3;   // batch-group 0..15
    const int CB  = blockIdx.x & 7;    // gate-column block 0..7 (32 units each)
    const int gb  = RB * 8;            // global batch base

    // ---------------- setup: load permuted weight slices into SMEM ----------------
    // permuted local column lc = unit_local*4 + gate  (gate: 0=i,1=f,2=g,3=o)
    #pragma unroll
    for (int g = 0; g < 4; g++) {
        const int gbase = g * UU + CB * 32;
        for (int i = tid; i < 256 * 32; i += NTHR) {
            int k = i >> 5, ul = i & 31;
            whs[k * 128 + ul * 4 + g] = Wh[k * G4 + gbase + ul];
        }
        for (int i = tid; i < 3 * 32; i += NTHR) {
            int f = i >> 5, ul = i & 31;
            wxs[f * 128 + ul * 4 + g] = Wx[f * G4 + gbase + ul];
        }
    }
    if (tid < 128) {
        int ul = tid >> 2, g = tid & 3;
        bs[tid] = bias[g * UU + CB * 32 + ul];
    }

    // GEMM thread mapping: each thread owns one (b_local, unit_local) pair -> 4 gate accs
    const int u_l = tid >> 3;   // 0..31
    const int b_l = tid & 7;    // 0..7

    float c = 0.f;

    // prefetch x[t=0]
    float xpre = 0.f;
    if (tid < 24) xpre = __ldg(&x[(size_t)(gb + tid / 3) * (TT * FF) + tid % 3]);

    __syncthreads();

    unsigned* barp = &g_bar[RB * 32];

    for (int s = 0; s < TT; s++) {
        // -------- stage h (prev step) from global into SMEM: hs[b][k], row stride 260 --------
        {
            const float4* hg = reinterpret_cast<const float4*>(g_h[s & 1] + (size_t)gb * UU);
            int bl = tid & 7;           // batch row
            int kb = tid >> 3;          // 0..31 -> covers k = kb*4..+3 and 128+kb*4..+3
            float4 v0 = __ldcg(hg + bl * 64 + kb);        // k = kb*4
            float4 v1 = __ldcg(hg + bl * 64 + 32 + kb);   // k = 128 + kb*4
            float* hrow = hs + bl * 260;
            *reinterpret_cast<float4*>(hrow + kb * 4)       = v0;
            *reinterpret_cast<float4*>(hrow + 128 + kb * 4) = v1;
        }
        if (tid < 24) xs[tid] = xpre;
        __syncthreads();

        // prefetch next step's x while GEMM runs
        if (tid < 24 && s + 1 < TT)
            xpre = __ldg(&x[(size_t)(gb + tid / 3) * (TT * FF) + (size_t)(s + 1) * FF + tid % 3]);

        // -------- acc init: bias + x @ Wx --------
        float4 bb4 = *reinterpret_cast<const float4*>(bs + u_l * 4);
        float a0 = bb4.x, a1 = bb4.y, a2 = bb4.z, a3 = bb4.w;
        {
            float xv0 = xs[b_l * 3 + 0], xv1 = xs[b_l * 3 + 1], xv2 = xs[b_l * 3 + 2];
            float4 w;
            w = *reinterpret_cast<const float4*>(wxs + 0 * 128 + u_l * 4);
            a0 = fmaf(xv0, w.x, a0); a1 = fmaf(xv0, w.y, a1);
            a2 = fmaf(xv0, w.z, a2); a3 = fmaf(xv0, w.w, a3);
            w = *reinterpret_cast<const float4*>(wxs + 1 * 128 + u_l * 4);
            a0 = fmaf(xv1, w.x, a0); a1 = fmaf(xv1, w.y, a1);
            a2 = fmaf(xv1, w.z, a2); a3 = fmaf(xv1, w.w, a3);
            w = *reinterpret_cast<const float4*>(wxs + 2 * 128 + u_l * 4);
            a0 = fmaf(xv2, w.x, a0); a1 = fmaf(xv2, w.y, a1);
            a2 = fmaf(xv2, w.z, a2); a3 = fmaf(xv2, w.w, a3);
        }

        // -------- GEMM: z += h @ Wh  (K=256) --------
        {
            const float* whp = whs + u_l * 4;
            const float* hp  = hs + b_l * 260;
            #pragma unroll 16
            for (int k = 0; k < UU; k++) {
                float  hv = hp[k];
                float4 wv = *reinterpret_cast<const float4*>(whp + k * 128);
                a0 = fmaf(hv, wv.x, a0);
                a1 = fmaf(hv, wv.y, a1);
                a2 = fmaf(hv, wv.z, a2);
                a3 = fmaf(hv, wv.w, a3);
            }
        }

        // -------- gates / state update --------
        {
            float ig = sig_f(a0);
            float fg = sig_f(a1);
            float gg = tanh_f(a2);
            float og = sig_f(a3);
            c = fmaf(fg, c, ig * gg);
            float hn = og * tanh_f(c);
            hns[b_l * 33 + u_l] = hn;
            if (s == TT - 1) cs[b_l * 33 + u_l] = c;
        }
        __syncthreads();

        // -------- coalesced stores: h_new -> global ping-pong + ys output --------
        {
            int b = tid >> 5, u = tid & 31;
            float v = hns[b * 33 + u];
            __stcg(&g_h[(s + 1) & 1][(size_t)(gb + b) * UU + CB * 32 + u], v);
            out[(size_t)(gb + b) * (TT * UU) + (size_t)s * UU + CB * 32 + u] = v;
            if (s == TT - 1 && write_hc) {
                out[(size_t)BB * TT * UU + (size_t)(gb + b) * UU + CB * 32 + u] = v;
                out[(size_t)BB * TT * UU + (size_t)BB * UU + (size_t)(gb + b) * UU + CB * 32 + u]
                    = cs[b * 33 + u];
            }
        }

        // -------- per-group barrier (8 CTAs), monotonic counter --------
        if (s + 1 < TT) {
            __syncthreads();
            if (tid == 0) {
                __threadfence();                 // release our h stores
                atomicAdd(barp, 1u);
                unsigned tgt = 8u * (unsigned)(s + 1);
                while (*((volatile unsigned*)barp) < tgt) { }
                __threadfence();                 // acquire peers' h stores
            }
            __syncthreads();
        }
    }
}

extern "C" void kernel_launch(void* const* d_in, const int* in_sizes, int n_in,
                              void* d_out, int out_size) {
    const float* x    = (const float*)d_in[0];
    const float* Wx   = (const float*)d_in[1];
    const float* Wh   = (const float*)d_in[2];
    const float* bias = (const float*)d_in[3];
    float* out = (float*)d_out;

    long long need = (long long)BB * TT * UU + 2LL * BB * UU;
    int write_hc = ((long long)out_size >= need) ? 1 : 0;

    cudaFuncSetAttribute(lstm_persistent_kernel,
                         cudaFuncAttributeMaxDynamicSharedMemorySize, SMEM_BYTES);

    lstm_init_kernel<<<256, 256>>>();
    lstm_persistent_kernel<<<NCTA, NTHR, SMEM_BYTES>>>(x, Wx, Wh, bias, out, write_hc);
}